// round 16
// baseline (speedup 1.0000x reference)
#include <cuda_runtime.h>
#include <cuda_fp16.h>

#define N_POINTS    32768
#define EMB         64
#define NUM_CLASSES 50
#define NUM_HOUSES  5
#define NUM_WIN     6            // NUM_WINDOWS + 1 (last = frame)
#define BOXES       (NUM_HOUSES * NUM_WIN)   // 30

// Output: data (N*64) | contains (50*N) | dists (50*30*N)
#define OUT_CONTAINS ((size_t)N_POINTS * EMB)
#define OUT_DISTS    (OUT_CONTAINS + (size_t)NUM_CLASSES * N_POINTS)

typedef unsigned int u32;

__device__ __forceinline__ u32 h2max(u32 a, u32 b) {
    u32 r; asm("max.f16x2 %0, %1, %2;" : "=r"(r) : "r"(a), "r"(b)); return r;
}
__device__ __forceinline__ u32 h2min(u32 a, u32 b) {
    u32 r; asm("min.f16x2 %0, %1, %2;" : "=r"(r) : "r"(a), "r"(b)); return r;
}
__device__ __forceinline__ u32 h2sub(u32 a, u32 b) {
    u32 r; asm("sub.rn.f16x2 %0, %1, %2;" : "=r"(r) : "r"(a), "r"(b)); return r;
}
__device__ __forceinline__ u32 h2add(u32 a, u32 b) {
    u32 r; asm("add.rn.f16x2 %0, %1, %2;" : "=r"(r) : "r"(a), "r"(b)); return r;
}
__device__ __forceinline__ u32 h2fma(u32 a, u32 b, u32 c) {
    u32 r; asm("fma.rn.f16x2 %0, %1, %2, %3;" : "=r"(r) : "r"(a), "r"(b), "r"(c)); return r;
}
__device__ __forceinline__ u32 h2mul(u32 a, u32 b) {
    u32 r; asm("mul.rn.f16x2 %0, %1, %2;" : "=r"(r) : "r"(a), "r"(b)); return r;
}
// pack two f32 -> f16x2 (lo in low half). cvt d, a, b: d.hi=a, d.lo=b.
__device__ __forceinline__ u32 packh2(float lo, float hi) {
    u32 r; asm("cvt.rn.f16x2.f32 %0, %1, %2;" : "=r"(r) : "f"(hi), "f"(lo)); return r;
}
__device__ __forceinline__ void h2tof32(u32 v, float& x, float& y) {
    asm("{\n\t.reg .b16 l, h;\n\tmov.b32 {l, h}, %2;\n\t"
        "cvt.f32.f16 %0, l;\n\tcvt.f32.f16 %1, h;\n\t}"
        : "=f"(x), "=f"(y) : "r"(v));
}

// One 2-dim fp16x2 step: clamp (HMNMX2 x2, alu) + sub + fma (fma pipe).
#define H2STEP_FMA(P, LO, HI, ACC) {                              \
    const u32 _d = h2sub((P), h2min(h2max((P), (LO)), (HI)));     \
    (ACC) = h2fma(_d, _d, (ACC)); }
#define H2STEP_MUL(P, LO, HI, ACC) {                              \
    const u32 _d = h2sub((P), h2min(h2max((P), (LO)), (HI)));     \
    (ACC) = h2mul(_d, _d); }

#define SLOT_STRIDE 9   // 8 data uint4 + 1 pad -> 144B group skew (4 banks)

__global__ __launch_bounds__(256, 4)
void geom_kernel(const float* __restrict__ data,
                 const float* __restrict__ shape,   // [50][5][6][2][64]
                 float* __restrict__ out)
{
    __shared__ uint4 s_box[BOXES][2 * SLOT_STRIDE];

    const int c   = blockIdx.y;
    const int tid = threadIdx.x;

    // ---- stage this class's 30 boxes as fp16x2 lo/hi pairs ----
    const float* sb = shape + (size_t)c * (BOXES * 2 * EMB);
    #pragma unroll
    for (int e = tid; e < BOXES * 16; e += 256) {
        const int box = e >> 4;
        const int s   = e & 15;           // slot: 4 dims
        const int d   = (s >> 3) * 32 + (s & 7) * 4;
        const float4 a = *reinterpret_cast<const float4*>(sb + box * 128 + d);
        const float4 b = *reinterpret_cast<const float4*>(sb + box * 128 + 64 + d);
        uint4 v;
        v.x = packh2(fminf(a.x, b.x), fminf(a.y, b.y));
        v.y = packh2(fmaxf(a.x, b.x), fmaxf(a.y, b.y));
        v.z = packh2(fminf(a.z, b.z), fminf(a.w, b.w));
        v.w = packh2(fmaxf(a.z, b.z), fmaxf(a.w, b.w));
        s_box[box][(s >> 3) * SLOT_STRIDE + (s & 7)] = v;
    }

    // ---- data passthrough (class-slice 0 only): linear block copy ----
    if (blockIdx.y == 0) {
        const float4* src = reinterpret_cast<const float4*>(
            data + (size_t)blockIdx.x * 256 * EMB);
        float4* dst = reinterpret_cast<float4*>(
            out + (size_t)blockIdx.x * 256 * EMB);
        #pragma unroll
        for (int k = 0; k < 16; k++)
            dst[tid + 256 * k] = src[tid + 256 * k];
    }
    __syncthreads();

    // ---- 2 threads per point, 2 points per thread: 32 points/warp ----
    const int lane = tid & 31;
    const int warp = tid >> 5;
    const int g    = lane >> 4;   // dim group: dims [g*32, g*32+32)
    const int i    = lane & 15;
    const int n0   = blockIdx.x * 256 + warp * 32 + i;   // and n0+16

    // 32 dims per point = 16 f16x2 pairs, two points
    u32 p0h[16], p1h[16];
    {
        const float4* dp0 = reinterpret_cast<const float4*>(
            data + (size_t)n0 * EMB + g * 32);
        const float4* dp1 = reinterpret_cast<const float4*>(
            data + (size_t)(n0 + 16) * EMB + g * 32);
        #pragma unroll
        for (int k = 0; k < 8; k++) {
            const float4 v0 = dp0[k];
            const float4 v1 = dp1[k];
            p0h[2 * k]     = packh2(v0.x, v0.y);
            p0h[2 * k + 1] = packh2(v0.z, v0.w);
            p1h[2 * k]     = packh2(v1.x, v1.y);
            p1h[2 * k + 1] = packh2(v1.z, v1.w);
        }
    }

    // dual-store: g==0 half stores point n0, g==1 half stores point n0+16.
    float* __restrict__ out_dists = out + OUT_DISTS
                                  + (size_t)c * BOXES * N_POINTS + n0
                                  + g * 16;

    bool town0 = false, town1 = false;
    #pragma unroll 1
    for (int h = 0; h < NUM_HOUSES; h++) {
        bool anyw0 = false, frame0 = false;
        bool anyw1 = false, frame1 = false;
        #pragma unroll 2
        for (int w = 0; w < NUM_WIN; w++) {
            const int box = h * NUM_WIN + w;
            const uint4* bx = &s_box[box][g * SLOT_STRIDE];
            // 8 accumulator chains (4 per point), each 4 HFMA2 deep
            u32 a0, a1, a2, a3, b0, b1, b2, b3;
            {
                const uint4 q = bx[0];
                H2STEP_MUL(p0h[0], q.x, q.y, a0)
                H2STEP_MUL(p0h[1], q.z, q.w, a1)
                H2STEP_MUL(p1h[0], q.x, q.y, b0)
                H2STEP_MUL(p1h[1], q.z, q.w, b1)
            }
            {
                const uint4 q = bx[1];
                H2STEP_MUL(p0h[2], q.x, q.y, a2)
                H2STEP_MUL(p0h[3], q.z, q.w, a3)
                H2STEP_MUL(p1h[2], q.x, q.y, b2)
                H2STEP_MUL(p1h[3], q.z, q.w, b3)
            }
            #pragma unroll
            for (int k = 2; k < 8; k += 2) {
                const uint4 q0 = bx[k];
                H2STEP_FMA(p0h[2 * k],     q0.x, q0.y, a0)
                H2STEP_FMA(p0h[2 * k + 1], q0.z, q0.w, a1)
                H2STEP_FMA(p1h[2 * k],     q0.x, q0.y, b0)
                H2STEP_FMA(p1h[2 * k + 1], q0.z, q0.w, b1)
                const uint4 q1 = bx[k + 1];
                H2STEP_FMA(p0h[2 * k + 2], q1.x, q1.y, a2)
                H2STEP_FMA(p0h[2 * k + 3], q1.z, q1.w, a3)
                H2STEP_FMA(p1h[2 * k + 2], q1.x, q1.y, b2)
                H2STEP_FMA(p1h[2 * k + 3], q1.z, q1.w, b3)
            }
            // combine chains, widen to fp32
            const u32 sa  = h2add(h2add(a0, a1), h2add(a2, a3));
            const u32 sb2 = h2add(h2add(b0, b1), h2add(b2, b3));
            float x0, y0, x1, y1;
            h2tof32(sa, x0, y0);
            h2tof32(sb2, x1, y1);
            float sq0 = x0 + y0;
            float sq1 = x1 + y1;
            // combine the two 32-dim halves (lanes xor 16)
            sq0 += __shfl_xor_sync(0xffffffffu, sq0, 16);
            sq1 += __shfl_xor_sync(0xffffffffu, sq1, 16);

            // inside <=> all fp16 deltas 0 <=> sq == 0 (partials >= 0)
            const bool ins0 = (sq0 == 0.0f);
            const bool ins1 = (sq1 == 0.0f);
            if (w < NUM_WIN - 1) { anyw0 |= ins0; anyw1 |= ins1; }
            else                 { frame0 = ins0; frame1 = ins1; }

            // each half-warp stores its own point: g==0 -> sq0, g==1 -> sq1
            const float sqm = g ? sq1 : sq0;
            float dm;
            asm("sqrt.approx.f32 %0, %1;" : "=f"(dm) : "f"(sqm));
            out_dists[(size_t)box * N_POINTS] = dm;
        }
        town0 |= (frame0 && !anyw0);
        town1 |= (frame1 && !anyw1);
    }

    // contains: g==0 stores point0, g==1 stores point1
    const bool townm = g ? town1 : town0;
    out[OUT_CONTAINS + (size_t)c * N_POINTS + n0 + g * 16] = townm ? 1.0f : 0.0f;
}

extern "C" void kernel_launch(void* const* d_in, const int* in_sizes, int n_in,
                              void* d_out, int out_size) {
    const float* data  = (const float*)d_in[0];
    const float* shape = (const float*)d_in[1];
    float* out = (float*)d_out;

    dim3 grid(N_POINTS / 256, NUM_CLASSES);
    geom_kernel<<<grid, 256>>>(data, shape, out);
}